// round 7
// baseline (speedup 1.0000x reference)
#include <cuda_runtime.h>
#include <cstdint>
#include <math.h>

#define NTOK 4096
#define DMODEL 1024
#define NEXP 8
#define DFF 4096

#define BM 128
#define BN 64
#define BK 16

#define PITCH_A 24    // floats per A row in smem (16 used); 24%32=24 -> conflict-free LDS.64
#define PITCH_B 136   // floats per B row in smem (128 used); 136%32=8 -> conflict-free LDS.64
#define APART (128 * PITCH_A)                  // 3072 floats
#define G1_STAGE (APART + 2 * 8 * PITCH_B)     // 5248 floats = 20992 B
#define G2_STAGE (APART + 8 * PITCH_B)         // 4160 floats = 16640 B
#define G1_STAGES 3
#define G2_STAGES 4
#define G1_SMEM (G1_STAGES * G1_STAGE * 4)     // 62976 B
#define G2_SMEM (G2_STAGES * G2_STAGE * 4)     // 66560 B

// ---------------- scratch (static device globals; no allocation) ----------------
__device__ int   g_counts[NEXP];
__device__ int   g_offsets[NEXP + 1];
__device__ int   g_cursor[NEXP];
__device__ int   g_slot_e[NTOK * 2];
__device__ float g_slot_w[NTOK * 2];
__device__ int   g_row_token[NTOK * 2];
__device__ float g_row_w[NTOK * 2];

// packed (tf32-converted, k-pair-interleaved) operands
__device__ float g_x_p [(size_t)NTOK * DMODEL];            // 16 MB
__device__ float g_wg_p[(size_t)NEXP * DMODEL * DFF];      // 134 MB
__device__ float g_wu_p[(size_t)NEXP * DMODEL * DFF];      // 134 MB
__device__ float g_wd_p[(size_t)NEXP * DFF * DMODEL];      // 134 MB
__device__ float g_H   [(size_t)NTOK * 2 * DFF];           // 134 MB (packed tf32)

// ---------------- helpers ----------------
__device__ __forceinline__ float qtf(float f) {
    uint32_t r;
    asm("cvt.rna.tf32.f32 %0, %1;" : "=r"(r) : "f"(f));
    return __uint_as_float(r);
}

__device__ __forceinline__ void mma_tf32(float c[4], const uint32_t a[4], const uint32_t b[2]) {
    asm volatile(
        "mma.sync.aligned.m16n8k8.row.col.f32.tf32.tf32.f32 "
        "{%0,%1,%2,%3}, {%4,%5,%6,%7}, {%8,%9}, {%0,%1,%2,%3};"
        : "+f"(c[0]), "+f"(c[1]), "+f"(c[2]), "+f"(c[3])
        : "r"(a[0]), "r"(a[1]), "r"(a[2]), "r"(a[3]), "r"(b[0]), "r"(b[1]));
}

__device__ __forceinline__ void cp16(void* dst, const void* src) {
    uint32_t d = (uint32_t)__cvta_generic_to_shared(dst);
    asm volatile("cp.async.cg.shared.global [%0], [%1], 16;" :: "r"(d), "l"(src));
}
#define CP_COMMIT() asm volatile("cp.async.commit_group;" ::: "memory")
#define CP_WAIT(n)  asm volatile("cp.async.wait_group %0;" :: "n"(n) : "memory")

// ---------------- pack: tf32-convert + k-pair interleave ----------------
// A-side rows (x, H): within each 8-block, store order [0,4,1,5,2,6,3,7]
//   -> float2 at pair-index q = (v[q], v[q+4])
// B-side (weights): out[e][k8][kk][n] pair = (w[k8*8+kk][n], w[k8*8+kk+4][n])
__global__ void pack_all_kernel(const float* __restrict__ x,
                                const float* __restrict__ wg,
                                const float* __restrict__ wu,
                                const float* __restrict__ wd) {
    if (blockIdx.x == 0 && threadIdx.x < NEXP) g_counts[threadIdx.x] = 0;

    size_t tid = (size_t)blockIdx.x * blockDim.x + threadIdx.x;
    size_t nth = (size_t)gridDim.x * blockDim.x;

    // wg + wu: rows of DFF pairs; row r = (e*128 + k8)*4 + kk
    const size_t WP1 = (size_t)NEXP * 128 * 4 * DFF;
    for (size_t i = tid; i < WP1; i += nth) {
        size_t n = i % DFF, r = i / DFF;
        size_t kk = r & 3, k8 = (r >> 2) & 127, e = r >> 9;
        size_t src = (e * DMODEL + k8 * 8 + kk) * DFF + n;
        ((float2*)g_wg_p)[i] = make_float2(qtf(wg[src]), qtf(wg[src + 4 * DFF]));
        ((float2*)g_wu_p)[i] = make_float2(qtf(wu[src]), qtf(wu[src + 4 * DFF]));
    }
    // wd: rows of DMODEL pairs; row r = (e*512 + k8)*4 + kk
    const size_t WP2 = (size_t)NEXP * 512 * 4 * DMODEL;
    for (size_t i = tid; i < WP2; i += nth) {
        size_t n = i % DMODEL, r = i / DMODEL;
        size_t kk = r & 3, k8 = (r >> 2) & 511, e = r >> 11;
        size_t src = (e * DFF + k8 * 8 + kk) * DMODEL + n;
        ((float2*)g_wd_p)[i] = make_float2(qtf(wd[src]), qtf(wd[src + 4 * DMODEL]));
    }
    // x: 8-blocks
    const size_t XB = (size_t)NTOK * DMODEL / 8;
    for (size_t i = tid; i < XB; i += nth) {
        const float4* src = (const float4*)(x + i * 8);
        float4 lo = src[0], hi = src[1];
        float4 o0 = make_float4(qtf(lo.x), qtf(hi.x), qtf(lo.y), qtf(hi.y));
        float4 o1 = make_float4(qtf(lo.z), qtf(hi.z), qtf(lo.w), qtf(hi.w));
        ((float4*)(g_x_p + i * 8))[0] = o0;
        ((float4*)(g_x_p + i * 8))[1] = o1;
    }
}

// ---------------- router: one warp per token ----------------
__global__ void router_kernel(const float* __restrict__ x,
                              const float* __restrict__ rw,
                              const float* __restrict__ rb,
                              float* __restrict__ probs_out,
                              float* __restrict__ idx_out) {
    int warp = (blockIdx.x * blockDim.x + threadIdx.x) >> 5;
    int lane = threadIdx.x & 31;
    if (warp >= NTOK) return;
    const float* xr = x + (size_t)warp * DMODEL;

    float acc[NEXP];
    #pragma unroll
    for (int e = 0; e < NEXP; e++) acc[e] = 0.f;

    for (int d = lane; d < DMODEL; d += 32) {
        float xv = xr[d];
        const float4* w4 = reinterpret_cast<const float4*>(rw + (size_t)d * NEXP);
        float4 w0 = w4[0], w1 = w4[1];
        acc[0] += xv * w0.x; acc[1] += xv * w0.y; acc[2] += xv * w0.z; acc[3] += xv * w0.w;
        acc[4] += xv * w1.x; acc[5] += xv * w1.y; acc[6] += xv * w1.z; acc[7] += xv * w1.w;
    }
    #pragma unroll
    for (int e = 0; e < NEXP; e++) {
        #pragma unroll
        for (int o = 16; o > 0; o >>= 1) acc[e] += __shfl_xor_sync(0xffffffffu, acc[e], o);
    }

    if (lane == 0) {
        float lg[NEXP];
        #pragma unroll
        for (int e = 0; e < NEXP; e++) lg[e] = acc[e] + rb[e];

        float m = lg[0];
        #pragma unroll
        for (int e = 1; e < NEXP; e++) m = fmaxf(m, lg[e]);
        float s = 0.f, p[NEXP];
        #pragma unroll
        for (int e = 0; e < NEXP; e++) { p[e] = expf(lg[e] - m); s += p[e]; }
        float inv = 1.f / s;
        #pragma unroll
        for (int e = 0; e < NEXP; e++) probs_out[(size_t)warp * NEXP + e] = p[e] * inv;

        int i0 = 0;
        #pragma unroll
        for (int e = 1; e < NEXP; e++) if (lg[e] > lg[i0]) i0 = e;
        int i1 = -1;
        #pragma unroll
        for (int e = 0; e < NEXP; e++) {
            if (e == i0) continue;
            if (i1 < 0 || lg[e] > lg[i1]) i1 = e;
        }
        float p0 = 1.f / (1.f + expf(lg[i1] - lg[i0]));
        float p1 = 1.f - p0;

        idx_out[warp * 2 + 0] = (float)i0;
        idx_out[warp * 2 + 1] = (float)i1;
        g_slot_e[warp * 2 + 0] = i0;
        g_slot_e[warp * 2 + 1] = i1;
        g_slot_w[warp * 2 + 0] = p0;
        g_slot_w[warp * 2 + 1] = p1;
        atomicAdd(&g_counts[i0], 1);
        atomicAdd(&g_counts[i1], 1);
    }
}

// ---------------- fused scan + list build ----------------
__global__ void finalize_kernel() {
    if (threadIdx.x == 0) {
        int off = 0;
        for (int e = 0; e < NEXP; e++) {
            g_offsets[e] = off;
            g_cursor[e]  = off;
            off += g_counts[e];
        }
        g_offsets[NEXP] = off;
    }
    __syncthreads();
    for (int t = threadIdx.x; t < NTOK; t += blockDim.x) {
        #pragma unroll
        for (int s = 0; s < 2; s++) {
            int e = g_slot_e[t * 2 + s];
            int pos = atomicAdd(&g_cursor[e], 1);
            g_row_token[pos] = t;
            g_row_w[pos] = g_slot_w[t * 2 + s];
        }
    }
}

// ---------------- GEMM1: H = silu(Xe@Wg+bg) * (Xe@Wu+bu) ----------------
// Packed tf32 operands, LDS.64 fragment loads, 3-stage cp.async pipeline.
__global__ __launch_bounds__(256, 2)
void gemm1_kernel(const float* __restrict__ bg, const float* __restrict__ bu) {
    extern __shared__ float smem[];
    int e = blockIdx.z;
    int off = g_offsets[e];
    int ne = g_offsets[e + 1] - off;
    int mbase = blockIdx.x * BM;
    if (mbase >= ne) return;
    int n0 = blockIdx.y * BN;

    int tid = threadIdx.x;
    int lane = tid & 31, warp = tid >> 5;
    int wm = (warp & 3) * 32;
    int wn = (warp >> 2) * 32;

    // A loader: row ra (0..127), chunk pair
    int ra = tid >> 1;
    int ca = (tid & 1) * 2;
    int arow = mbase + ra;
    const float* gA = g_x_p + (size_t)g_row_token[off + (arow < ne ? arow : 0)] * DMODEL + ca * 4;
    // B loader: row rb (0..7), chunk cb (0..31)
    int rb = tid >> 5;
    int cb = tid & 31;
    size_t bstride = 2 * (size_t)DFF;
    const float* gBg = g_wg_p + ((size_t)(e * 128) * 4 + (rb & 3)) * bstride + (size_t)n0 * 2 + cb * 4;
    const float* gBu = g_wu_p + ((size_t)(e * 128) * 4 + (rb & 3)) * bstride + (size_t)n0 * 2 + cb * 4;
    int rbk = rb >> 2;   // ks within stage

    float accG[2][4][4], accU[2][4][4];
    #pragma unroll
    for (int mi = 0; mi < 2; mi++)
        #pragma unroll
        for (int ni = 0; ni < 4; ni++)
            #pragma unroll
            for (int q = 0; q < 4; q++) { accG[mi][ni][q] = 0.f; accU[mi][ni][q] = 0.f; }

    const int KT = DMODEL / BK;   // 64

    #define G1_PREFETCH(kt, st) do {                                              \
        float* base = smem + (st) * G1_STAGE;                                     \
        cp16(base + ra * PITCH_A + ca * 4,     gA + (kt) * 16);                   \
        cp16(base + ra * PITCH_A + ca * 4 + 4, gA + (kt) * 16 + 4);               \
        size_t brow = (size_t)((2 * (kt) + rbk) * 4) * bstride;                   \
        cp16(base + APART + rb * PITCH_B + cb * 4,                gBg + brow);    \
        cp16(base + APART + 8 * PITCH_B + rb * PITCH_B + cb * 4,  gBu + brow);    \
        CP_COMMIT();                                                              \
    } while (0)

    G1_PREFETCH(0, 0);
    G1_PREFETCH(1, 1);

    for (int kt = 0; kt < KT; kt++) {
        CP_WAIT(1);
        __syncthreads();
        if (kt + 2 < KT) G1_PREFETCH(kt + 2, (kt + 2) % G1_STAGES);
        else CP_COMMIT();

        const float* st = smem + (kt % G1_STAGES) * G1_STAGE;
        const float2* A2 = (const float2*)st;
        const float2* Bg2 = (const float2*)(st + APART);
        const float2* Bu2 = (const float2*)(st + APART + 8 * PITCH_B);

        #pragma unroll
        for (int ks = 0; ks < 2; ks++) {
            int acol = ks * 4 + (lane & 3);          // float2 index within A row
            uint32_t afr[2][4];
            #pragma unroll
            for (int mi = 0; mi < 2; mi++) {
                int m = wm + mi * 16 + (lane >> 2);
                float2 v0 = A2[m * (PITCH_A / 2) + acol];
                float2 v1 = A2[(m + 8) * (PITCH_A / 2) + acol];
                afr[mi][0] = __float_as_uint(v0.x);
                afr[mi][1] = __float_as_uint(v1.x);
                afr[mi][2] = __float_as_uint(v0.y);
                afr[mi][3] = __float_as_uint(v1.y);
            }
            int brow0 = (ks * 4 + (lane & 3)) * (PITCH_B / 2);
            uint32_t bgfr[4][2], bufr[4][2];
            #pragma unroll
            for (int ni = 0; ni < 4; ni++) {
                int n = wn + ni * 8 + (lane >> 2);
                float2 vg = Bg2[brow0 + n];
                float2 vu = Bu2[brow0 + n];
                bgfr[ni][0] = __float_as_uint(vg.x);
                bgfr[ni][1] = __float_as_uint(vg.y);
                bufr[ni][0] = __float_as_uint(vu.x);
                bufr[ni][1] = __float_as_uint(vu.y);
            }
            #pragma unroll
            for (int mi = 0; mi < 2; mi++)
                #pragma unroll
                for (int ni = 0; ni < 4; ni++) {
                    mma_tf32(accG[mi][ni], afr[mi], bgfr[ni]);
                    mma_tf32(accU[mi][ni], afr[mi], bufr[ni]);
                }
        }
    }
    #undef G1_PREFETCH

    // epilogue: silu(g)*u -> packed tf32 H
    int jj = (lane & 3) * 2;
    int p0 = (jj < 4) ? 2 * jj : 2 * (jj - 4) + 1;
    int p1 = (jj + 1 < 4) ? 2 * (jj + 1) : 2 * (jj - 3) + 1;
    const float* bgp = bg + (size_t)e * DFF + n0;
    const float* bup = bu + (size_t)e * DFF + n0;
    #pragma unroll
    for (int mi = 0; mi < 2; mi++) {
        int r0 = mbase + wm + mi * 16 + (lane >> 2);
        #pragma unroll
        for (int ni = 0; ni < 4; ni++) {
            int nc = wn + ni * 8 + jj;
            float bg0 = bgp[nc], bg1 = bgp[nc + 1];
            float bu0 = bup[nc], bu1 = bup[nc + 1];
            size_t base8 = (size_t)n0 + wn + ni * 8;
            if (r0 < ne) {
                size_t base = (size_t)(off + r0) * DFF + base8;
                float g = accG[mi][ni][0] + bg0, u = accU[mi][ni][0] + bu0;
                g_H[base + p0] = qtf((g / (1.f + expf(-g))) * u);
                g = accG[mi][ni][1] + bg1; u = accU[mi][ni][1] + bu1;
                g_H[base + p1] = qtf((g / (1.f + expf(-g))) * u);
            }
            if (r0 + 8 < ne) {
                size_t base = (size_t)(off + r0 + 8) * DFF + base8;
                float g = accG[mi][ni][2] + bg0, u = accU[mi][ni][2] + bu0;
                g_H[base + p0] = qtf((g / (1.f + expf(-g))) * u);
                g = accG[mi][ni][3] + bg1; u = accU[mi][ni][3] + bu1;
                g_H[base + p1] = qtf((g / (1.f + expf(-g))) * u);
            }
        }
    }
}

// ---------------- GEMM2: out[token] += w * (H_e @ Wd_e + bd) ----------------
// Packed tf32 operands, LDS.64 fragment loads, 4-stage cp.async pipeline.
__global__ __launch_bounds__(256, 2)
void gemm2_kernel(const float* __restrict__ bd, float* __restrict__ out) {
    extern __shared__ float smem[];
    int e = blockIdx.z;
    int off = g_offsets[e];
    int ne = g_offsets[e + 1] - off;
    int mbase = blockIdx.x * BM;
    if (mbase >= ne) return;
    int n0 = blockIdx.y * BN;

    int tid = threadIdx.x;
    int lane = tid & 31, warp = tid >> 5;
    int wm = (warp & 3) * 32;
    int wn = (warp >> 2) * 32;

    int ra = tid >> 1;
    int ca = (tid & 1) * 2;
    int arow = mbase + ra;
    const float* gA = g_H + (size_t)(off + (arow < ne ? arow : 0)) * DFF + ca * 4;

    int rb = tid >> 5;
    int cb = tid & 31;
    size_t bstride = 2 * (size_t)DMODEL;
    const float* gB = g_wd_p + ((size_t)(e * 512) * 4 + (rb & 3)) * bstride + (size_t)n0 * 2 + cb * 4;
    int rbk = rb >> 2;

    float acc[2][4][4];
    #pragma unroll
    for (int mi = 0; mi < 2; mi++)
        #pragma unroll
        for (int ni = 0; ni < 4; ni++)
            #pragma unroll
            for (int q = 0; q < 4; q++) acc[mi][ni][q] = 0.f;

    const int KT = DFF / BK;   // 256

    #define G2_PREFETCH(kt, st) do {                                              \
        float* base = smem + (st) * G2_STAGE;                                     \
        cp16(base + ra * PITCH_A + ca * 4,     gA + (kt) * 16);                   \
        cp16(base + ra * PITCH_A + ca * 4 + 4, gA + (kt) * 16 + 4);               \
        size_t brow = (size_t)((2 * (kt) + rbk) * 4) * bstride;                   \
        cp16(base + APART + rb * PITCH_B + cb * 4, gB + brow);                    \
        CP_COMMIT();                                                              \
    } while (0)

    G2_PREFETCH(0, 0);
    G2_PREFETCH(1, 1);
    G2_PREFETCH(2, 2);

    for (int kt = 0; kt < KT; kt++) {
        CP_WAIT(2);
        __syncthreads();
        if (kt + 3 < KT) G2_PREFETCH(kt + 3, (kt + 3) % G2_STAGES);
        else CP_COMMIT();

        const float* st = smem + (kt % G2_STAGES) * G2_STAGE;
        const float2* A2 = (const float2*)st;
        const float2* B2 = (const float2*)(st + APART);

        #pragma unroll
        for (int ks = 0; ks < 2; ks++) {
            int acol = ks * 4 + (lane & 3);
            uint32_t afr[2][4];
            #pragma unroll
            for (int mi = 0; mi < 2; mi++) {
                int m = wm + mi * 16 + (lane >> 2);
                float2 v0 = A2[m * (PITCH_A / 2) + acol];
                float2 v1 = A2[(m + 8) * (PITCH_A / 2) + acol];
                afr[mi][0] = __float_as_uint(v0.x);
                afr[mi][1] = __float_as_uint(v1.x);
                afr[mi][2] = __float_as_uint(v0.y);
                afr[mi][3] = __float_as_uint(v1.y);
            }
            int brow0 = (ks * 4 + (lane & 3)) * (PITCH_B / 2);
            uint32_t bfr[4][2];
            #pragma unroll
            for (int ni = 0; ni < 4; ni++) {
                int n = wn + ni * 8 + (lane >> 2);
                float2 v = B2[brow0 + n];
                bfr[ni][0] = __float_as_uint(v.x);
                bfr[ni][1] = __float_as_uint(v.y);
            }
            #pragma unroll
            for (int mi = 0; mi < 2; mi++)
                #pragma unroll
                for (int ni = 0; ni < 4; ni++)
                    mma_tf32(acc[mi][ni], afr[mi], bfr[ni]);
        }
    }
    #undef G2_PREFETCH

    // epilogue: weighted scatter-add into out
    const float* bdp = bd + (size_t)e * DMODEL + n0;
    #pragma unroll
    for (int mi = 0; mi < 2; mi++) {
        int r0 = mbase + wm + mi * 16 + (lane >> 2);
        #pragma unroll
        for (int ni = 0; ni < 4; ni++) {
            int nc = wn + ni * 8 + (lane & 3) * 2;
            float b0 = bdp[nc], b1 = bdp[nc + 1];
            if (r0 < ne) {
                int tokr = g_row_token[off + r0];
                float w = g_row_w[off + r0];
                float* op = out + (size_t)tokr * DMODEL + n0 + nc;
                atomicAdd(op,     w * (acc[mi][ni][0] + b0));
                atomicAdd(op + 1, w * (acc[mi][ni][1] + b1));
            }
            if (r0 + 8 < ne) {
                int tokr = g_row_token[off + r0 + 8];
                float w = g_row_w[off + r0 + 8];
                float* op = out + (size_t)tokr * DMODEL + n0 + nc;
                atomicAdd(op,     w * (acc[mi][ni][2] + b0));
                atomicAdd(op + 1, w * (acc[mi][ni][3] + b1));
            }
        }
    }
}

// ---------------- launch ----------------
extern "C" void kernel_launch(void* const* d_in, const int* in_sizes, int n_in,
                              void* d_out, int out_size) {
    const float* x  = (const float*)d_in[0];
    const float* rw = (const float*)d_in[1];
    const float* rb = (const float*)d_in[2];
    const float* wg = (const float*)d_in[3];
    const float* bg = (const float*)d_in[4];
    const float* wu = (const float*)d_in[5];
    const float* bu = (const float*)d_in[6];
    const float* wd = (const float*)d_in[7];
    const float* bd = (const float*)d_in[8];

    float* out   = (float*)d_out;
    float* probs = out + (size_t)NTOK * DMODEL;
    float* idx   = probs + (size_t)NTOK * NEXP;

    cudaFuncSetAttribute(gemm1_kernel, cudaFuncAttributeMaxDynamicSharedMemorySize, G1_SMEM);
    cudaFuncSetAttribute(gemm2_kernel, cudaFuncAttributeMaxDynamicSharedMemorySize, G2_SMEM);

    cudaMemsetAsync(out, 0, (size_t)NTOK * DMODEL * sizeof(float));
    pack_all_kernel<<<4096, 256>>>(x, wg, wu, wd);
    router_kernel<<<NTOK / 4, 128>>>(x, rw, rb, probs, idx);
    finalize_kernel<<<1, 256>>>();
    gemm1_kernel<<<dim3(NTOK / BM, DFF / BN, NEXP), 256, G1_SMEM>>>(bg, bu);
    gemm2_kernel<<<dim3(NTOK / BM, DMODEL / BN, NEXP), 256, G2_SMEM>>>(bd, out);
}

// round 9
// speedup vs baseline: 1.1645x; 1.1645x over previous
#include <cuda_runtime.h>
#include <cstdint>
#include <math.h>

#define NTOK 4096
#define DMODEL 1024
#define NEXP 8
#define DFF 4096

#define BM 128
#define BN 64
#define BK 16

#define PA 20
#define PB 20
#define G1_BG_OFF (128 * PA)              // 2560 floats
#define G1_BU_OFF (G1_BG_OFF + 64 * PB)   // 3840
#define G1_STAGE_F (G1_BU_OFF + 64 * PB)  // 5120 floats = 20480 B
#define G2_B_OFF (128 * PA)
#define G2_STAGE_F (G2_B_OFF + 64 * PB)   // 3840 floats = 15360 B
#define G1_STAGES 3
#define G2_STAGES 4
#define G1_SMEM (G1_STAGES * G1_STAGE_F * 4)   // 61440 B
#define G2_SMEM (G2_STAGES * G2_STAGE_F * 4)   // 61440 B

// ---------------- scratch (static device globals; no allocation) ----------------
__device__ int   g_counts[NEXP];
__device__ int   g_offsets[NEXP + 1];
__device__ int   g_cursor[NEXP];
__device__ int   g_slot_e[NTOK * 2];
__device__ float g_slot_w[NTOK * 2];
__device__ int   g_row_token[NTOK * 2];
__device__ float g_row_w[NTOK * 2];

__device__ float g_x_p [(size_t)NTOK * DMODEL];          // tf32, k-major (plain)
__device__ float g_wg_p[(size_t)NEXP * DFF * DMODEL];    // tf32, n-major [e][n][k]
__device__ float g_wu_p[(size_t)NEXP * DFF * DMODEL];    // tf32, n-major [e][n][k]
__device__ float g_wd_p[(size_t)NEXP * DMODEL * DFF];    // tf32, n-major [e][n][k]
__device__ float g_H   [(size_t)NTOK * 2 * DFF];         // tf32, k-major (plain)

// ---------------- helpers ----------------
__device__ __forceinline__ float qtf(float f) {
    uint32_t r;
    asm("cvt.rna.tf32.f32 %0, %1;" : "=r"(r) : "f"(f));
    return __uint_as_float(r);
}

__device__ __forceinline__ void mma_tf32(float c[4], const uint32_t a[4], const uint32_t b[2]) {
    asm volatile(
        "mma.sync.aligned.m16n8k8.row.col.f32.tf32.tf32.f32 "
        "{%0,%1,%2,%3}, {%4,%5,%6,%7}, {%8,%9}, {%0,%1,%2,%3};"
        : "+f"(c[0]), "+f"(c[1]), "+f"(c[2]), "+f"(c[3])
        : "r"(a[0]), "r"(a[1]), "r"(a[2]), "r"(a[3]), "r"(b[0]), "r"(b[1]));
}

__device__ __forceinline__ void ldsm4(uint32_t* r, uint32_t addr) {
    asm volatile("ldmatrix.sync.aligned.m8n8.x4.shared.b16 {%0,%1,%2,%3}, [%4];"
        : "=r"(r[0]), "=r"(r[1]), "=r"(r[2]), "=r"(r[3]) : "r"(addr));
}

__device__ __forceinline__ void cp16(void* dst, const void* src) {
    uint32_t d = (uint32_t)__cvta_generic_to_shared(dst);
    asm volatile("cp.async.cg.shared.global [%0], [%1], 16;" :: "r"(d), "l"(src));
}
#define CP_COMMIT() asm volatile("cp.async.commit_group;" ::: "memory")
#define CP_WAIT(n)  asm volatile("cp.async.wait_group %0;" :: "n"(n) : "memory")

// ---------------- pack: tf32-convert + transpose weights to n-major ----------------
// z < 8 : wg+wu expert z  (K=DMODEL, N=DFF)    x = n-tile, y = k-tile
// z >= 8: wd    expert z-8 (K=DFF, N=DMODEL)   x = k-tile, y = n-tile
__global__ void pack_w_kernel(const float* __restrict__ wg,
                              const float* __restrict__ wu,
                              const float* __restrict__ wd) {
    __shared__ float tg[32][33];
    __shared__ float tu[32][33];
    int z = blockIdx.z;
    int tx = threadIdx.x, ty = threadIdx.y;
    if (z == 0 && blockIdx.x == 0 && blockIdx.y == 0 && ty == 0 && tx < NEXP)
        g_counts[tx] = 0;

    if (z < 8) {
        size_t e = z;
        size_t kb = (size_t)blockIdx.y * 32, nb = (size_t)blockIdx.x * 32;
        #pragma unroll
        for (int i = 0; i < 4; i++) {
            size_t k = kb + ty + i * 8;
            tg[ty + i * 8][tx] = qtf(wg[(e * DMODEL + k) * DFF + nb + tx]);
            tu[ty + i * 8][tx] = qtf(wu[(e * DMODEL + k) * DFF + nb + tx]);
        }
        __syncthreads();
        #pragma unroll
        for (int i = 0; i < 4; i++) {
            size_t n = nb + ty + i * 8;
            g_wg_p[(e * DFF + n) * DMODEL + kb + tx] = tg[tx][ty + i * 8];
            g_wu_p[(e * DFF + n) * DMODEL + kb + tx] = tu[tx][ty + i * 8];
        }
    } else {
        size_t e = z - 8;
        size_t kb = (size_t)blockIdx.x * 32, nb = (size_t)blockIdx.y * 32;
        #pragma unroll
        for (int i = 0; i < 4; i++) {
            size_t k = kb + ty + i * 8;
            tg[ty + i * 8][tx] = qtf(wd[(e * DFF + k) * DMODEL + nb + tx]);
        }
        __syncthreads();
        #pragma unroll
        for (int i = 0; i < 4; i++) {
            size_t n = nb + ty + i * 8;
            g_wd_p[(e * DMODEL + n) * DFF + kb + tx] = tg[tx][ty + i * 8];
        }
    }
}

// ---------------- router (+ x tf32 pack): one warp per token ----------------
__global__ void router_kernel(const float* __restrict__ x,
                              const float* __restrict__ rw,
                              const float* __restrict__ rb,
                              float* __restrict__ probs_out,
                              float* __restrict__ idx_out) {
    // pack this block's 4 tokens of x into g_x_p (tf32)
    {
        size_t base = (size_t)blockIdx.x * 4 * DMODEL;
        const float4* src = (const float4*)(x + base);
        float4* dst = (float4*)(g_x_p + base);
        for (int i = threadIdx.x; i < 4 * DMODEL / 4; i += 128) {
            float4 v = src[i];
            dst[i] = make_float4(qtf(v.x), qtf(v.y), qtf(v.z), qtf(v.w));
        }
    }

    int warp = (blockIdx.x * blockDim.x + threadIdx.x) >> 5;
    int lane = threadIdx.x & 31;
    if (warp >= NTOK) return;
    const float* xr = x + (size_t)warp * DMODEL;

    float acc[NEXP];
    #pragma unroll
    for (int e = 0; e < NEXP; e++) acc[e] = 0.f;

    for (int d = lane; d < DMODEL; d += 32) {
        float xv = xr[d];
        const float4* w4 = reinterpret_cast<const float4*>(rw + (size_t)d * NEXP);
        float4 w0 = w4[0], w1 = w4[1];
        acc[0] += xv * w0.x; acc[1] += xv * w0.y; acc[2] += xv * w0.z; acc[3] += xv * w0.w;
        acc[4] += xv * w1.x; acc[5] += xv * w1.y; acc[6] += xv * w1.z; acc[7] += xv * w1.w;
    }
    #pragma unroll
    for (int e = 0; e < NEXP; e++) {
        #pragma unroll
        for (int o = 16; o > 0; o >>= 1) acc[e] += __shfl_xor_sync(0xffffffffu, acc[e], o);
    }

    if (lane == 0) {
        float lg[NEXP];
        #pragma unroll
        for (int e = 0; e < NEXP; e++) lg[e] = acc[e] + rb[e];

        float m = lg[0];
        #pragma unroll
        for (int e = 1; e < NEXP; e++) m = fmaxf(m, lg[e]);
        float s = 0.f, p[NEXP];
        #pragma unroll
        for (int e = 0; e < NEXP; e++) { p[e] = expf(lg[e] - m); s += p[e]; }
        float inv = 1.f / s;
        #pragma unroll
        for (int e = 0; e < NEXP; e++) probs_out[(size_t)warp * NEXP + e] = p[e] * inv;

        int i0 = 0;
        #pragma unroll
        for (int e = 1; e < NEXP; e++) if (lg[e] > lg[i0]) i0 = e;
        int i1 = -1;
        #pragma unroll
        for (int e = 0; e < NEXP; e++) {
            if (e == i0) continue;
            if (i1 < 0 || lg[e] > lg[i1]) i1 = e;
        }
        float p0 = 1.f / (1.f + expf(lg[i1] - lg[i0]));
        float p1 = 1.f - p0;

        idx_out[warp * 2 + 0] = (float)i0;
        idx_out[warp * 2 + 1] = (float)i1;
        g_slot_e[warp * 2 + 0] = i0;
        g_slot_e[warp * 2 + 1] = i1;
        g_slot_w[warp * 2 + 0] = p0;
        g_slot_w[warp * 2 + 1] = p1;
        atomicAdd(&g_counts[i0], 1);
        atomicAdd(&g_counts[i1], 1);
    }
}

// ---------------- fused scan + list build ----------------
__global__ void finalize_kernel() {
    if (threadIdx.x == 0) {
        int off = 0;
        for (int e = 0; e < NEXP; e++) {
            g_offsets[e] = off;
            g_cursor[e]  = off;
            off += g_counts[e];
        }
        g_offsets[NEXP] = off;
    }
    __syncthreads();
    for (int t = threadIdx.x; t < NTOK; t += blockDim.x) {
        #pragma unroll
        for (int s = 0; s < 2; s++) {
            int e = g_slot_e[t * 2 + s];
            int pos = atomicAdd(&g_cursor[e], 1);
            g_row_token[pos] = t;
            g_row_w[pos] = g_slot_w[t * 2 + s];
        }
    }
}

// ---------------- GEMM1: H = silu(Xe@Wg+bg) * (Xe@Wu+bu) ----------------
// ldmatrix fragments, 3-stage cp.async pipeline.
__global__ __launch_bounds__(256, 2)
void gemm1_kernel(const float* __restrict__ bg, const float* __restrict__ bu) {
    extern __shared__ float smem[];
    int e = blockIdx.z;
    int off = g_offsets[e];
    int ne = g_offsets[e + 1] - off;
    int mbase = blockIdx.x * BM;
    if (mbase >= ne) return;
    int n0 = blockIdx.y * BN;

    int tid = threadIdx.x;
    int lane = tid & 31, warp = tid >> 5;
    int wm = (warp & 3) * 32;
    int wn = (warp >> 2) * 32;

    // cp.async loader: thread covers A rows ra, ra+64 and Bg/Bu n-row ra, 16B chunk kc
    int ra = tid >> 2;
    int kc = (tid & 3) * 4;
    int ar0 = mbase + ra, ar1 = mbase + ra + 64;
    const float* gA0 = g_x_p + (size_t)g_row_token[off + (ar0 < ne ? ar0 : 0)] * DMODEL + kc;
    const float* gA1 = g_x_p + (size_t)g_row_token[off + (ar1 < ne ? ar1 : 0)] * DMODEL + kc;
    const float* gBg = g_wg_p + ((size_t)e * DFF + n0 + ra) * DMODEL + kc;
    const float* gBu = g_wu_p + ((size_t)e * DFF + n0 + ra) * DMODEL + kc;
    int da0 = ra * PA + kc, da1 = (ra + 64) * PA + kc;
    int db  = ra * PB + kc;

    // ldmatrix lane addresses
    uint32_t sbase = (uint32_t)__cvta_generic_to_shared(smem);
    int rowa = ((lane >> 3) & 1) * 8 + (lane & 7);
    int koffa = (lane >> 4) * 4;
    int rowb = (lane >> 4) * 8 + (lane & 7);
    int koffb = ((lane >> 3) & 1) * 4;
    uint32_t aAddr[2], bgAddr[2], buAddr[2];
    #pragma unroll
    for (int mi = 0; mi < 2; mi++)
        aAddr[mi] = sbase + ((wm + mi * 16 + rowa) * PA + koffa) * 4;
    #pragma unroll
    for (int p = 0; p < 2; p++) {
        bgAddr[p] = sbase + (G1_BG_OFF + (wn + p * 16 + rowb) * PB + koffb) * 4;
        buAddr[p] = sbase + (G1_BU_OFF + (wn + p * 16 + rowb) * PB + koffb) * 4;
    }

    float accG[2][4][4], accU[2][4][4];
    #pragma unroll
    for (int mi = 0; mi < 2; mi++)
        #pragma unroll
        for (int ni = 0; ni < 4; ni++)
            #pragma unroll
            for (int q = 0; q < 4; q++) { accG[mi][ni][q] = 0.f; accU[mi][ni][q] = 0.f; }

    const int KT = DMODEL / BK;   // 64

    #define G1_PREFETCH(kt, st) do {                                   \
        float* b = smem + (st) * G1_STAGE_F;                           \
        cp16(b + da0,            gA0 + (kt) * 16);                     \
        cp16(b + da1,            gA1 + (kt) * 16);                     \
        cp16(b + G1_BG_OFF + db, gBg + (kt) * 16);                     \
        cp16(b + G1_BU_OFF + db, gBu + (kt) * 16);                     \
        CP_COMMIT();                                                   \
    } while (0)

    G1_PREFETCH(0, 0);
    G1_PREFETCH(1, 1);

    for (int kt = 0; kt < KT; kt++) {
        CP_WAIT(1);
        __syncthreads();
        if (kt + 2 < KT) G1_PREFETCH(kt + 2, (kt + 2) % G1_STAGES);
        else CP_COMMIT();

        uint32_t so = (uint32_t)((kt % G1_STAGES) * G1_STAGE_F * 4);
        #pragma unroll
        for (int ks = 0; ks < 2; ks++) {
            uint32_t kso = so + ks * 32;
            uint32_t af[2][4], bgf[2][4], buf[2][4];
            ldsm4(af[0], aAddr[0] + kso);
            ldsm4(af[1], aAddr[1] + kso);
            ldsm4(bgf[0], bgAddr[0] + kso);
            ldsm4(bgf[1], bgAddr[1] + kso);
            ldsm4(buf[0], buAddr[0] + kso);
            ldsm4(buf[1], buAddr[1] + kso);
            #pragma unroll
            for (int mi = 0; mi < 2; mi++)
                #pragma unroll
                for (int p = 0; p < 2; p++) {
                    mma_tf32(accG[mi][2 * p],     af[mi], &bgf[p][0]);
                    mma_tf32(accG[mi][2 * p + 1], af[mi], &bgf[p][2]);
                    mma_tf32(accU[mi][2 * p],     af[mi], &buf[p][0]);
                    mma_tf32(accU[mi][2 * p + 1], af[mi], &buf[p][2]);
                }
        }
    }
    #undef G1_PREFETCH

    // epilogue: silu(g)*u -> tf32 H (plain layout)
    const float* bgp = bg + (size_t)e * DFF + n0;
    const float* bup = bu + (size_t)e * DFF + n0;
    #pragma unroll
    for (int mi = 0; mi < 2; mi++) {
        int r0 = mbase + wm + mi * 16 + (lane >> 2);
        #pragma unroll
        for (int ni = 0; ni < 4; ni++) {
            int nc = wn + ni * 8 + (lane & 3) * 2;
            float bg0 = bgp[nc], bg1 = bgp[nc + 1];
            float bu0 = bup[nc], bu1 = bup[nc + 1];
            if (r0 < ne) {
                size_t base = (size_t)(off + r0) * DFF + n0 + nc;
                float g = accG[mi][ni][0] + bg0, u = accU[mi][ni][0] + bu0;
                g_H[base] = qtf((g / (1.f + expf(-g))) * u);
                g = accG[mi][ni][1] + bg1; u = accU[mi][ni][1] + bu1;
                g_H[base + 1] = qtf((g / (1.f + expf(-g))) * u);
            }
            if (r0 + 8 < ne) {
                size_t base = (size_t)(off + r0 + 8) * DFF + n0 + nc;
                float g = accG[mi][ni][2] + bg0, u = accU[mi][ni][2] + bu0;
                g_H[base] = qtf((g / (1.f + expf(-g))) * u);
                g = accG[mi][ni][3] + bg1; u = accU[mi][ni][3] + bu1;
                g_H[base + 1] = qtf((g / (1.f + expf(-g))) * u);
            }
        }
    }
}

// ---------------- GEMM2: out[token] += w * (H_e @ Wd_e + bd) ----------------
// ldmatrix fragments, 4-stage cp.async pipeline.
__global__ __launch_bounds__(256, 2)
void gemm2_kernel(const float* __restrict__ bd, float* __restrict__ out) {
    extern __shared__ float smem[];
    int e = blockIdx.z;
    int off = g_offsets[e];
    int ne = g_offsets[e + 1] - off;
    int mbase = blockIdx.x * BM;
    if (mbase >= ne) return;
    int n0 = blockIdx.y * BN;

    int tid = threadIdx.x;
    int lane = tid & 31, warp = tid >> 5;
    int wm = (warp & 3) * 32;
    int wn = (warp >> 2) * 32;

    int ra = tid >> 2;
    int kc = (tid & 3) * 4;
    int ar0 = mbase + ra, ar1 = mbase + ra + 64;
    const float* gA0 = g_H + (size_t)(off + (ar0 < ne ? ar0 : 0)) * DFF + kc;
    const float* gA1 = g_H + (size_t)(off + (ar1 < ne ? ar1 : 0)) * DFF + kc;
    const float* gB  = g_wd_p + ((size_t)e * DMODEL + n0 + ra) * DFF + kc;
    int da0 = ra * PA + kc, da1 = (ra + 64) * PA + kc;
    int db  = ra * PB + kc;

    uint32_t sbase = (uint32_t)__cvta_generic_to_shared(smem);
    int rowa = ((lane >> 3) & 1) * 8 + (lane & 7);
    int koffa = (lane >> 4) * 4;
    int rowb = (lane >> 4) * 8 + (lane & 7);
    int koffb = ((lane >> 3) & 1) * 4;
    uint32_t aAddr[2], bAddr[2];
    #pragma unroll
    for (int mi = 0; mi < 2; mi++)
        aAddr[mi] = sbase + ((wm + mi * 16 + rowa) * PA + koffa) * 4;
    #pragma unroll
    for (int p = 0; p < 2; p++)
        bAddr[p] = sbase + (G2_B_OFF + (wn + p * 16 + rowb) * PB + koffb) * 4;

    float acc[2][4][4];
    #pragma unroll
    for (int mi = 0; mi < 2; mi++)
        #pragma unroll
        for (int ni = 0; ni < 4; ni++)
            #pragma unroll
            for (int q = 0; q < 4; q++) acc[mi][ni][q] = 0.f;

    const int KT = DFF / BK;   // 256

    #define G2_PREFETCH(kt, st) do {                                   \
        float* b = smem + (st) * G2_STAGE_F;                           \
        cp16(b + da0,           gA0 + (kt) * 16);                      \
        cp16(b + da1,           gA1 + (kt) * 16);                      \
        cp16(b + G2_B_OFF + db, gB + (kt) * 16);                       \
        CP_COMMIT();                                                   \
    } while (0)

    G2_PREFETCH(0, 0);
    G2_PREFETCH(1, 1);
    G2_PREFETCH(2, 2);

    for (int kt = 0; kt < KT; kt++) {
        CP_WAIT(2);
        __syncthreads();
        if (kt + 3 < KT) G2_PREFETCH(kt + 3, (kt + 3) % G2_STAGES);
        else CP_COMMIT();

        uint32_t so = (uint32_t)((kt % G2_STAGES) * G2_STAGE_F * 4);
        #pragma unroll
        for (int ks = 0; ks < 2; ks++) {
            uint32_t kso = so + ks * 32;
            uint32_t af[2][4], bf[2][4];
            ldsm4(af[0], aAddr[0] + kso);
            ldsm4(af[1], aAddr[1] + kso);
            ldsm4(bf[0], bAddr[0] + kso);
            ldsm4(bf[1], bAddr[1] + kso);
            #pragma unroll
            for (int mi = 0; mi < 2; mi++)
                #pragma unroll
                for (int p = 0; p < 2; p++) {
                    mma_tf32(acc[mi][2 * p],     af[mi], &bf[p][0]);
                    mma_tf32(acc[mi][2 * p + 1], af[mi], &bf[p][2]);
                }
        }
    }
    #undef G2_PREFETCH

    // epilogue: weighted scatter-add into out
    const float* bdp = bd + (size_t)e * DMODEL + n0;
    #pragma unroll
    for (int mi = 0; mi < 2; mi++) {
        int r0 = mbase + wm + mi * 16 + (lane >> 2);
        #pragma unroll
        for (int ni = 0; ni < 4; ni++) {
            int nc = wn + ni * 8 + (lane & 3) * 2;
            float b0 = bdp[nc], b1 = bdp[nc + 1];
            if (r0 < ne) {
                int tokr = g_row_token[off + r0];
                float w = g_row_w[off + r0];
                float* op = out + (size_t)tokr * DMODEL + n0 + nc;
                atomicAdd(op,     w * (acc[mi][ni][0] + b0));
                atomicAdd(op + 1, w * (acc[mi][ni][1] + b1));
            }
            if (r0 + 8 < ne) {
                int tokr = g_row_token[off + r0 + 8];
                float w = g_row_w[off + r0 + 8];
                float* op = out + (size_t)tokr * DMODEL + n0 + nc;
                atomicAdd(op,     w * (acc[mi][ni][2] + b0));
                atomicAdd(op + 1, w * (acc[mi][ni][3] + b1));
            }
        }
    }
}

// ---------------- launch ----------------
extern "C" void kernel_launch(void* const* d_in, const int* in_sizes, int n_in,
                              void* d_out, int out_size) {
    const float* x  = (const float*)d_in[0];
    const float* rw = (const float*)d_in[1];
    const float* rb = (const float*)d_in[2];
    const float* wg = (const float*)d_in[3];
    const float* bg = (const float*)d_in[4];
    const float* wu = (const float*)d_in[5];
    const float* bu = (const float*)d_in[6];
    const float* wd = (const float*)d_in[7];
    const float* bd = (const float*)d_in[8];

    float* out   = (float*)d_out;
    float* probs = out + (size_t)NTOK * DMODEL;
    float* idx   = probs + (size_t)NTOK * NEXP;

    cudaFuncSetAttribute(gemm1_kernel, cudaFuncAttributeMaxDynamicSharedMemorySize, G1_SMEM);
    cudaFuncSetAttribute(gemm2_kernel, cudaFuncAttributeMaxDynamicSharedMemorySize, G2_SMEM);

    cudaMemsetAsync(out, 0, (size_t)NTOK * DMODEL * sizeof(float));
    pack_w_kernel<<<dim3(128, 32, 16), dim3(32, 8)>>>(wg, wu, wd);
    router_kernel<<<NTOK / 4, 128>>>(x, rw, rb, probs, idx);
    finalize_kernel<<<1, 256>>>();
    gemm1_kernel<<<dim3(NTOK / BM, DFF / BN, NEXP), 256, G1_SMEM>>>(bg, bu);
    gemm2_kernel<<<dim3(NTOK / BM, DMODEL / BN, NEXP), 256, G2_SMEM>>>(bd, out);
}